// round 15
// baseline (speedup 1.0000x reference)
#include <cuda_runtime.h>
#include <cuda_fp16.h>

// Problem constants
#define Bx 8
#define Lx 256
#define Dx 256
#define BLD (Bx*Lx*Dx)   // 524288
#define BLL (Bx*Lx*Lx)   // 524288

typedef unsigned int u32;
typedef unsigned long long u64;

// Scratch (device globals — no allocation allowed)
__device__ float g_A[BLD], g_Bm[BLD], g_H[BLD];
__device__ float g_W[BLL];

// ---- fp16 m16n8k16 mma (fp32 accum) ---------------------------------------
__device__ __forceinline__ void mma_f16(float c[4], const u32 a[4], const u32 b[2]) {
    asm volatile(
        "mma.sync.aligned.m16n8k16.row.col.f32.f16.f16.f32 "
        "{%0,%1,%2,%3},{%4,%5,%6,%7},{%8,%9},{%0,%1,%2,%3};"
        : "+f"(c[0]), "+f"(c[1]), "+f"(c[2]), "+f"(c[3])
        : "r"(a[0]), "r"(a[1]), "r"(a[2]), "r"(a[3]), "r"(b[0]), "r"(b[1]));
}
__device__ __forceinline__ u32 h2u(float x, float y) {
    __half2 h = __floats2half2_rn(x, y);
    return *reinterpret_cast<u32*>(&h);
}
__device__ __forceinline__ u64 packh4(float4 v) {   // (k,k+1)|(k+2,k+3) fp16x4
    return ((u64)h2u(v.z, v.w) << 32) | (u64)h2u(v.x, v.y);
}

// ---- ldmatrix helpers -------------------------------------------------------
__device__ __forceinline__ u32 s2u(const void* p) {
    return (u32)__cvta_generic_to_shared(p);
}
__device__ __forceinline__ void ldsm4(u32& r0, u32& r1, u32& r2, u32& r3, u32 a) {
    asm volatile("ldmatrix.sync.aligned.m8n8.x4.shared.b16 {%0,%1,%2,%3}, [%4];"
        : "=r"(r0), "=r"(r1), "=r"(r2), "=r"(r3) : "r"(a));
}
__device__ __forceinline__ void ldsm2(u32& r0, u32& r1, u32 a) {
    asm volatile("ldmatrix.sync.aligned.m8n8.x2.shared.b16 {%0,%1}, [%2];"
        : "=r"(r0), "=r"(r1) : "r"(a));
}

// ---- packed f32x2 helpers (edge kernel) ------------------------------------
__device__ __forceinline__ u64 pack2(float lo, float hi) {
    u64 r; asm("mov.b64 %0,{%1,%2};" : "=l"(r) : "f"(lo), "f"(hi)); return r;
}
__device__ __forceinline__ void unpack2(u64 v, float& lo, float& hi) {
    asm("mov.b64 {%0,%1},%2;" : "=f"(lo), "=f"(hi) : "l"(v));
}
__device__ __forceinline__ u64 ffma2(u64 a, u64 b, u64 c) {
    u64 d; asm("fma.rn.f32x2 %0,%1,%2,%3;" : "=l"(d) : "l"(a), "l"(b), "l"(c)); return d;
}
__device__ __forceinline__ u64 fadd2(u64 a, u64 b) {
    u64 d; asm("add.rn.f32x2 %0,%1,%2;" : "=l"(d) : "l"(a), "l"(b)); return d;
}
__device__ __forceinline__ u64 fmax2z(u64 a) {
    float lo, hi; unpack2(a, lo, hi);
    return pack2(fmaxf(lo, 0.f), fmaxf(hi, 0.f));
}

// ---------------------------------------------------------------------------
// Kernel 1: projections via fp16 HMMA + ldmatrix, full-K coalesced staging.
// Block 64m x 64n, 256 thr = 8 warps (2m32 x 4n16), warp tile 32x16.
// Smem [row][kp], stride 132 (LDSM rows hit disjoint 16B regions: no
// conflicts). Per chunk: 2 LDSM.x4 (A) + 2 LDSM.x2 (B) + 4 HMMA.
// grid (32, 4, 3) = 384 blocks.
// ---------------------------------------------------------------------------
#define XW_STRIDE 132
#define PROJ_SMEM (2 * 64 * XW_STRIDE * 4)

__global__ __launch_bounds__(256) void proj_kernel(
    const float* __restrict__ Q,
    const float* __restrict__ Wa,
    const float* __restrict__ Wb,
    const float* __restrict__ Wd)
{
    extern __shared__ u32 sm[];
    u32* Xh = sm;                        // [row][kp], stride 132
    u32* Wh = sm + 64 * XW_STRIDE;

    int mat = blockIdx.z;
    const float* W = (mat == 0) ? Wa : (mat == 1) ? Wb : Wd;
    float* Out     = (mat == 0) ? g_A : (mat == 1) ? g_Bm : g_H;

    int tid  = threadIdx.x;
    int m0 = blockIdx.x * 64, n0 = blockIdx.y * 64;
    int wid = tid >> 5, lane = tid & 31;
    int wm = wid & 1;
    int wn = wid >> 1;
    int lg = lane >> 2, lk = lane & 3;

#pragma unroll
    for (int p = 0; p < 16; p++) {
        int idx = p * 256 + tid;
        int row = idx >> 6, c4 = idx & 63;
        float4 xv = *(const float4*)(Q + (m0 + row) * Dx + c4 * 4);
        float4 wv = *(const float4*)(W + (n0 + row) * Dx + c4 * 4);
        *(u64*)&Xh[row * XW_STRIDE + c4 * 2] = packh4(xv);
        *(u64*)&Wh[row * XW_STRIDE + c4 * 2] = packh4(wv);
    }
    __syncthreads();

    // LDSM lane address components
    int lm = lane & 15, lh = lane >> 4;        // A: row-in-16, k-half
    int l8 = lane & 7,  lb = (lane >> 3) & 1;  // B: row-in-8, k-half
    u32 xb0 = s2u(&Xh[(wm * 32 + lm) * XW_STRIDE + lh * 4]);
    u32 xb1 = s2u(&Xh[(wm * 32 + 16 + lm) * XW_STRIDE + lh * 4]);
    u32 wb0 = s2u(&Wh[(wn * 16 + l8) * XW_STRIDE + lb * 4]);
    u32 wb1 = s2u(&Wh[(wn * 16 + 8 + l8) * XW_STRIDE + lb * 4]);

    float c[2][2][4];
#pragma unroll
    for (int mt = 0; mt < 2; mt++)
#pragma unroll
        for (int nt = 0; nt < 2; nt++)
#pragma unroll
            for (int q = 0; q < 4; q++) c[mt][nt][q] = 0.f;

#pragma unroll
    for (int ck = 0; ck < 16; ck++) {
        u32 koff = ck * 8 * 4;   // kp byte offset
        u32 a[2][4], bfr[2][2];
        ldsm4(a[0][0], a[0][1], a[0][2], a[0][3], xb0 + koff);
        ldsm4(a[1][0], a[1][1], a[1][2], a[1][3], xb1 + koff);
        ldsm2(bfr[0][0], bfr[0][1], wb0 + koff);
        ldsm2(bfr[1][0], bfr[1][1], wb1 + koff);
#pragma unroll
        for (int mt = 0; mt < 2; mt++)
#pragma unroll
            for (int nt = 0; nt < 2; nt++)
                mma_f16(c[mt][nt], a[mt], bfr[nt]);
    }

#pragma unroll
    for (int mt = 0; mt < 2; mt++) {
        int row = m0 + wm * 32 + mt * 16 + lg;
#pragma unroll
        for (int nt = 0; nt < 2; nt++) {
            int col = n0 + wn * 16 + nt * 8 + 2 * lk;
            *(float2*)(Out + row * Dx + col)       = make_float2(c[mt][nt][0], c[mt][nt][1]);
            *(float2*)(Out + (row + 8) * Dx + col) = make_float2(c[mt][nt][2], c[mt][nt][3]);
        }
    }
}

// ---------------------------------------------------------------------------
// Kernel 2: edge scores + mask + softmax -> g_W, tail casts folded in. (R8)
// ---------------------------------------------------------------------------
__global__ __launch_bounds__(256) void edge_kernel(
    const int* __restrict__ dep,
    const float* __restrict__ w2,
    const int* __restrict__ wl,
    float* __restrict__ dst)   // out + BLD, or nullptr
{
    int b  = blockIdx.y;
    int i0 = blockIdx.x * 8;

    __shared__ __align__(16) float Ash2[8][520];
    __shared__ __align__(16) float w2d[512];
    __shared__ __align__(16) float Bt[2][16][258];
    __shared__ float redmx[2][8], redsum[2][8];

    int tid = threadIdx.x;

#pragma unroll
    for (int p = 0; p < 2; p++) {
        int e = tid * 4 + p * 1024;
        int il = e >> 8, cc = e & 255;
        float4 v = *(const float4*)(g_A + (b * Lx + i0 + il) * Dx + cc);
        *(u64*)&Ash2[il][2 * cc]     = pack2(v.x, v.x);
        *(u64*)&Ash2[il][2 * cc + 2] = pack2(v.y, v.y);
        *(u64*)&Ash2[il][2 * cc + 4] = pack2(v.z, v.z);
        *(u64*)&Ash2[il][2 * cc + 6] = pack2(v.w, v.w);
    }
    {
        float v = w2[tid];
        *(u64*)&w2d[2 * tid] = pack2(v, v);
    }
    if (dst && blockIdx.x == 0 && blockIdx.y == 0 && tid < Bx)
        dst[tid] = (float)wl[tid];
    float* depout = dst ? dst + Bx : nullptr;

    const float* Bbase = g_Bm + b * Lx * Dx;

    float4 pf[4];
#pragma unroll
    for (int p = 0; p < 4; p++) {
        int e = tid * 4 + p * 1024;
        int j = e >> 4, cl = e & 15;
        pf[p] = *(const float4*)(Bbase + j * Dx + cl);
    }
#pragma unroll
    for (int p = 0; p < 4; p++) {
        int e = tid * 4 + p * 1024;
        int j = e >> 4, cl = e & 15;
        Bt[0][cl + 0][j] = pf[p].x; Bt[0][cl + 1][j] = pf[p].y;
        Bt[0][cl + 2][j] = pf[p].z; Bt[0][cl + 3][j] = pf[p].w;
    }
    __syncthreads();

    int w  = tid >> 5;
    int jl = tid & 31;
    int jh = w >> 2;
    int wr = w & 3;
    int r0 = wr * 2, r1 = r0 + 1;
    int jbase = jh * 128;

    u64 acc0[2] = {0, 0}, acc1[2] = {0, 0};

#pragma unroll 1
    for (int ch = 0; ch < 16; ch++) {
        int buf = ch & 1;
        if (ch < 15) {
            int c0 = (ch + 1) * 16;
#pragma unroll
            for (int p = 0; p < 4; p++) {
                int e = tid * 4 + p * 1024;
                int j = e >> 4, cl = e & 15;
                pf[p] = *(const float4*)(Bbase + j * Dx + c0 + cl);
            }
        }
#pragma unroll
        for (int c2 = 0; c2 < 8; c2++) {
            int cbase = ch * 16 + c2 * 2;
            ulonglong2 A0 = *(const ulonglong2*)&Ash2[r0][cbase * 2];
            ulonglong2 A1 = *(const ulonglong2*)&Ash2[r1][cbase * 2];
            ulonglong2 UU = *(const ulonglong2*)&w2d[cbase * 2];
#pragma unroll
            for (int cc = 0; cc < 2; cc++) {
                u64 a0 = cc ? A0.y : A0.x;
                u64 a1 = cc ? A1.y : A1.x;
                u64 up = cc ? UU.y : UU.x;
                int cl = c2 * 2 + cc;
#pragma unroll
                for (int gp = 0; gp < 2; gp++) {
                    u64 bt = *(const u64*)&Bt[buf][cl][jbase + gp * 64 + jl * 2];
                    acc0[gp] = ffma2(fmax2z(fadd2(a0, bt)), up, acc0[gp]);
                    acc1[gp] = ffma2(fmax2z(fadd2(a1, bt)), up, acc1[gp]);
                }
            }
        }
        if (ch < 15) {
            int nb = buf ^ 1;
#pragma unroll
            for (int p = 0; p < 4; p++) {
                int e = tid * 4 + p * 1024;
                int j = e >> 4, cl = e & 15;
                Bt[nb][cl + 0][j] = pf[p].x; Bt[nb][cl + 1][j] = pf[p].y;
                Bt[nb][cl + 2][j] = pf[p].z; Bt[nb][cl + 3][j] = pf[p].w;
            }
            __syncthreads();
        }
    }

    int gi0 = b * Lx + i0 + r0;
    int gi1 = b * Lx + i0 + r1;
    float T0[4], T1[4];
    int   mk0[4], mk1[4];
    float mx0 = -1e30f, mx1 = -1e30f;
#pragma unroll
    for (int gp = 0; gp < 2; gp++) {
        int j0 = jbase + gp * 64 + jl * 2;
        int2 m0v = *(const int2*)(dep + gi0 * Lx + j0);
        int2 m1v = *(const int2*)(dep + gi1 * Lx + j0);
        float lo, hi;
        unpack2(acc0[gp], lo, hi);
        mk0[2*gp]   = (m0v.x > 0);
        mk0[2*gp+1] = (m0v.y > 0);
        T0[2*gp]    = mk0[2*gp]   ? lo : -100.0f;
        T0[2*gp+1]  = mk0[2*gp+1] ? hi : -100.0f;
        unpack2(acc1[gp], lo, hi);
        mk1[2*gp]   = (m1v.x > 0);
        mk1[2*gp+1] = (m1v.y > 0);
        T1[2*gp]    = mk1[2*gp]   ? lo : -100.0f;
        T1[2*gp+1]  = mk1[2*gp+1] ? hi : -100.0f;
        mx0 = fmaxf(mx0, fmaxf(T0[2*gp], T0[2*gp+1]));
        mx1 = fmaxf(mx1, fmaxf(T1[2*gp], T1[2*gp+1]));
        if (depout) {
            *(float2*)(depout + gi0 * Lx + j0) = make_float2((float)m0v.x, (float)m0v.y);
            *(float2*)(depout + gi1 * Lx + j0) = make_float2((float)m1v.x, (float)m1v.y);
        }
    }
#pragma unroll
    for (int off = 16; off > 0; off >>= 1) {
        mx0 = fmaxf(mx0, __shfl_xor_sync(0xffffffffu, mx0, off));
        mx1 = fmaxf(mx1, __shfl_xor_sync(0xffffffffu, mx1, off));
    }
    if (jl == 0) { redmx[jh][r0] = mx0; redmx[jh][r1] = mx1; }
    __syncthreads();
    float gmx0 = fmaxf(redmx[0][r0], redmx[1][r0]);
    float gmx1 = fmaxf(redmx[0][r1], redmx[1][r1]);

    float E0[4], E1[4], sum0 = 0.f, sum1 = 0.f;
#pragma unroll
    for (int g = 0; g < 4; g++) {
        E0[g] = expf(T0[g] - gmx0); sum0 += E0[g];
        E1[g] = expf(T1[g] - gmx1); sum1 += E1[g];
    }
#pragma unroll
    for (int off = 16; off > 0; off >>= 1) {
        sum0 += __shfl_xor_sync(0xffffffffu, sum0, off);
        sum1 += __shfl_xor_sync(0xffffffffu, sum1, off);
    }
    if (jl == 0) { redsum[jh][r0] = sum0; redsum[jh][r1] = sum1; }
    __syncthreads();
    float inv0 = 1.0f / (redsum[0][r0] + redsum[1][r0]);
    float inv1 = 1.0f / (redsum[0][r1] + redsum[1][r1]);

#pragma unroll
    for (int gp = 0; gp < 2; gp++) {
        int j0 = jbase + gp * 64 + jl * 2;
        float2 o0, o1;
        o0.x = mk0[2*gp]   ? E0[2*gp]   * inv0 : 0.f;
        o0.y = mk0[2*gp+1] ? E0[2*gp+1] * inv0 : 0.f;
        o1.x = mk1[2*gp]   ? E1[2*gp]   * inv1 : 0.f;
        o1.y = mk1[2*gp+1] ? E1[2*gp+1] * inv1 : 0.f;
        *(float2*)(g_W + gi0 * Lx + j0) = o0;
        *(float2*)(g_W + gi1 * Lx + j0) = o1;
    }
}

// ---------------------------------------------------------------------------
// Kernel 3: agg via fp16 HMMA + ldmatrix (A-side). out = relu(Q + w@H).
// Block 64i x 64c, 256 thr = 8 warps (2m32 x 4n16), warp tile 32x16.
// Wt [i][kp] stride 132 (LDSM.x4 A-side); Hs [kp][c] stride 72 (plain LDS,
// layout not LDSM-compatible). grid (4,4,8) = 128 blocks.
// ---------------------------------------------------------------------------
#define AGG_SMEM ((64 * XW_STRIDE + 128 * 72) * 4)

__global__ __launch_bounds__(256) void agg_kernel(
    const float* __restrict__ Q,
    float* __restrict__ out)
{
    extern __shared__ u32 sm[];
    u32* Wt = sm;                       // [i][kp], stride 132
    u32* Hs = sm + 64 * XW_STRIDE;      // [kp][c], stride 72

    int b  = blockIdx.z;
    int i0 = blockIdx.x * 64;
    int c0 = blockIdx.y * 64;

    int tid = threadIdx.x;
    int wid = tid >> 5, lane = tid & 31;
    int wm = wid & 1;
    int wn = wid >> 1;
    int lg = lane >> 2, lk = lane & 3;

    // ---- stage all W (64 rows x 256 j), coalesced
#pragma unroll
    for (int p = 0; p < 16; p++) {
        int idx = p * 256 + tid;
        int row = idx >> 6, c4 = idx & 63;
        float4 v = *(const float4*)(g_W + (b * Lx + i0 + row) * Lx + c4 * 4);
        *(u64*)&Wt[row * XW_STRIDE + c4 * 2] = packh4(v);
    }
    // ---- stage all H (256 j x 64 c)
#pragma unroll
    for (int p = 0; p < 16; p++) {
        int idx = p * 256 + tid;
        int kp = idx >> 5, c2 = (idx & 31) * 2;
        const float* Hg = g_H + (b * Lx + 2 * kp) * Dx + c0 + c2;
        float2 h0 = *(const float2*)Hg;
        float2 h1 = *(const float2*)(Hg + Dx);
        Hs[kp * 72 + c2]     = h2u(h0.x, h1.x);
        Hs[kp * 72 + c2 + 1] = h2u(h0.y, h1.y);
    }
    __syncthreads();

    int lm = lane & 15, lh = lane >> 4;
    u32 wb0 = s2u(&Wt[(wm * 32 + lm) * XW_STRIDE + lh * 4]);
    u32 wb1 = s2u(&Wt[(wm * 32 + 16 + lm) * XW_STRIDE + lh * 4]);

    float c[2][2][4];
#pragma unroll
    for (int mt = 0; mt < 2; mt++)
#pragma unroll
        for (int nt = 0; nt < 2; nt++)
#pragma unroll
            for (int q = 0; q < 4; q++) c[mt][nt][q] = 0.f;

#pragma unroll
    for (int ck = 0; ck < 16; ck++) {
        int kc = ck * 8;
        u32 koff = (u32)kc * 4;
        u32 a[2][4], bfr[2][2];
        ldsm4(a[0][0], a[0][1], a[0][2], a[0][3], wb0 + koff);
        ldsm4(a[1][0], a[1][1], a[1][2], a[1][3], wb1 + koff);
#pragma unroll
        for (int nt = 0; nt < 2; nt++) {
            int cb = wn * 16 + nt * 8;
            bfr[nt][0] = Hs[(kc + lk) * 72 + cb + lg];
            bfr[nt][1] = Hs[(kc + lk + 4) * 72 + cb + lg];
        }
#pragma unroll
        for (int mt = 0; mt < 2; mt++)
#pragma unroll
            for (int nt = 0; nt < 2; nt++)
                mma_f16(c[mt][nt], a[mt], bfr[nt]);
    }

#pragma unroll
    for (int mt = 0; mt < 2; mt++) {
        int row = i0 + wm * 32 + mt * 16 + lg;
#pragma unroll
        for (int nt = 0; nt < 2; nt++) {
            int col = c0 + wn * 16 + nt * 8 + 2 * lk;
            long base0 = (long)(b * Lx + row) * Dx + col;
            long base1 = (long)(b * Lx + row + 8) * Dx + col;
            float2 q0 = *(const float2*)(Q + base0);
            float2 q1 = *(const float2*)(Q + base1);
            *(float2*)(out + base0) = make_float2(fmaxf(q0.x + c[mt][nt][0], 0.f),
                                                  fmaxf(q0.y + c[mt][nt][1], 0.f));
            *(float2*)(out + base1) = make_float2(fmaxf(q1.x + c[mt][nt][2], 0.f),
                                                  fmaxf(q1.y + c[mt][nt][3], 0.f));
        }
    }
}

// ---------------------------------------------------------------------------
extern "C" void kernel_launch(void* const* d_in, const int* in_sizes, int n_in,
                              void* d_out, int out_size)
{
    const float* Q   = (const float*)d_in[0];
    const int*   wl  = (const int*)d_in[1];
    const int*   dep = (const int*)d_in[2];
    const float* Wa  = (const float*)d_in[3];
    const float* Wb  = (const float*)d_in[4];
    const float* w2  = (const float*)d_in[5];
    const float* Wd  = (const float*)d_in[6];
    float* out = (float*)d_out;

    float* dst = (out_size >= BLD + Bx + BLL) ? out + BLD : nullptr;

    static bool attr_set = false;
    if (!attr_set) {
        cudaFuncSetAttribute(proj_kernel, cudaFuncAttributeMaxDynamicSharedMemorySize, PROJ_SMEM);
        cudaFuncSetAttribute(agg_kernel,  cudaFuncAttributeMaxDynamicSharedMemorySize, AGG_SMEM);
        attr_set = true;
    }

    // projections via fp16 HMMA + ldmatrix (384 blocks)
    proj_kernel<<<dim3(32, 4, 3), 256, PROJ_SMEM>>>(Q, Wa, Wb, Wd);
    // edge scores + softmax -> g_W (+ tail casts) (256 blocks)
    edge_kernel<<<dim3(32, Bx), 256>>>(dep, w2, wl, dst);
    // aggregation via fp16 HMMA + ldmatrix A-side + fused residual relu
    agg_kernel<<<dim3(4, 4, Bx), 256, AGG_SMEM>>>(Q, out);
}

// round 16
// speedup vs baseline: 1.0063x; 1.0063x over previous
#include <cuda_runtime.h>
#include <cuda_fp16.h>

// Problem constants
#define Bx 8
#define Lx 256
#define Dx 256
#define BLD (Bx*Lx*Dx)   // 524288
#define BLL (Bx*Lx*Lx)   // 524288

typedef unsigned int u32;
typedef unsigned long long u64;

// Scratch (device globals — no allocation allowed)
__device__ float g_A[BLD], g_Bm[BLD], g_H[BLD];
__device__ float g_W[BLL];

// ---- fp16 m16n8k16 mma (fp32 accum) ---------------------------------------
__device__ __forceinline__ void mma_f16(float c[4], const u32 a[4], const u32 b[2]) {
    asm volatile(
        "mma.sync.aligned.m16n8k16.row.col.f32.f16.f16.f32 "
        "{%0,%1,%2,%3},{%4,%5,%6,%7},{%8,%9},{%0,%1,%2,%3};"
        : "+f"(c[0]), "+f"(c[1]), "+f"(c[2]), "+f"(c[3])
        : "r"(a[0]), "r"(a[1]), "r"(a[2]), "r"(a[3]), "r"(b[0]), "r"(b[1]));
}
__device__ __forceinline__ u32 h2u(float x, float y) {
    __half2 h = __floats2half2_rn(x, y);
    return *reinterpret_cast<u32*>(&h);
}
__device__ __forceinline__ u64 packh4(float4 v) {   // (k,k+1)|(k+2,k+3) fp16x4
    return ((u64)h2u(v.z, v.w) << 32) | (u64)h2u(v.x, v.y);
}

// ---- ldmatrix helpers -------------------------------------------------------
__device__ __forceinline__ u32 s2u(const void* p) {
    return (u32)__cvta_generic_to_shared(p);
}
__device__ __forceinline__ void ldsm4(u32& r0, u32& r1, u32& r2, u32& r3, u32 a) {
    asm volatile("ldmatrix.sync.aligned.m8n8.x4.shared.b16 {%0,%1,%2,%3}, [%4];"
        : "=r"(r0), "=r"(r1), "=r"(r2), "=r"(r3) : "r"(a));
}
__device__ __forceinline__ void ldsm2(u32& r0, u32& r1, u32 a) {
    asm volatile("ldmatrix.sync.aligned.m8n8.x2.shared.b16 {%0,%1}, [%2];"
        : "=r"(r0), "=r"(r1) : "r"(a));
}

// ---- packed f32x2 helpers (edge kernel) ------------------------------------
__device__ __forceinline__ u64 pack2(float lo, float hi) {
    u64 r; asm("mov.b64 %0,{%1,%2};" : "=l"(r) : "f"(lo), "f"(hi)); return r;
}
__device__ __forceinline__ void unpack2(u64 v, float& lo, float& hi) {
    asm("mov.b64 {%0,%1},%2;" : "=f"(lo), "=f"(hi) : "l"(v));
}
__device__ __forceinline__ u64 ffma2(u64 a, u64 b, u64 c) {
    u64 d; asm("fma.rn.f32x2 %0,%1,%2,%3;" : "=l"(d) : "l"(a), "l"(b), "l"(c)); return d;
}
__device__ __forceinline__ u64 fadd2(u64 a, u64 b) {
    u64 d; asm("add.rn.f32x2 %0,%1,%2;" : "=l"(d) : "l"(a), "l"(b)); return d;
}
__device__ __forceinline__ u64 fmax2z(u64 a) {
    float lo, hi; unpack2(a, lo, hi);
    return pack2(fmaxf(lo, 0.f), fmaxf(hi, 0.f));
}

// ---------------------------------------------------------------------------
// Kernel 1: ALL THREE projections fused per CTA (X staged once).
// Block 64m x 64n, 256 thr = 8 warps (2m32 x 4n16), warp tile 32x16.
// Smem: Xh + Wa/Wb/Wd tiles, [row][kp] stride 132 (verified conflict-free,
// LDSM-compatible). 135 KB smem -> 1 CTA/SM; grid (32,4) = 128 CTAs, 1 wave.
// Per mat: 16 chunks of (2 LDSM.x4 + 2 LDSM.x2 + 4 HMMA), zero barriers.
// ---------------------------------------------------------------------------
#define XW_STRIDE 132
#define PROJ_SMEM (4 * 64 * XW_STRIDE * 4)

__global__ __launch_bounds__(256) void proj_kernel(
    const float* __restrict__ Q,
    const float* __restrict__ Wa,
    const float* __restrict__ Wb,
    const float* __restrict__ Wd)
{
    extern __shared__ u32 sm[];
    u32* Xh = sm;   // [row][kp], stride 132; Wh[mat] follow

    int tid  = threadIdx.x;
    int m0 = blockIdx.x * 64, n0 = blockIdx.y * 64;
    int wid = tid >> 5, lane = tid & 31;
    int wm = wid & 1;
    int wn = wid >> 1;
    int lg = lane >> 2, lk = lane & 3;

    // ---- stage X (64 rows x 256 k), coalesced
#pragma unroll
    for (int p = 0; p < 16; p++) {
        int idx = p * 256 + tid;
        int row = idx >> 6, c4 = idx & 63;
        float4 xv = *(const float4*)(Q + (m0 + row) * Dx + c4 * 4);
        *(u64*)&Xh[row * XW_STRIDE + c4 * 2] = packh4(xv);
    }
    // ---- stage Wa, Wb, Wd tiles (64 rows x 256 k each), coalesced
#pragma unroll
    for (int mat = 0; mat < 3; mat++) {
        const float* W = (mat == 0) ? Wa : (mat == 1) ? Wb : Wd;
        u32* Wh = sm + (1 + mat) * 64 * XW_STRIDE;
#pragma unroll
        for (int p = 0; p < 16; p++) {
            int idx = p * 256 + tid;
            int row = idx >> 6, c4 = idx & 63;
            float4 wv = *(const float4*)(W + (n0 + row) * Dx + c4 * 4);
            *(u64*)&Wh[row * XW_STRIDE + c4 * 2] = packh4(wv);
        }
    }
    __syncthreads();

    // LDSM lane address components (verified R15 mapping)
    int lm = lane & 15, lh = lane >> 4;        // A: row-in-16, k-half
    int l8 = lane & 7,  lb = (lane >> 3) & 1;  // B: row-in-8, k-half
    u32 xb0 = s2u(&Xh[(wm * 32 + lm) * XW_STRIDE + lh * 4]);
    u32 xb1 = s2u(&Xh[(wm * 32 + 16 + lm) * XW_STRIDE + lh * 4]);

#pragma unroll
    for (int mat = 0; mat < 3; mat++) {
        u32* Wh = sm + (1 + mat) * 64 * XW_STRIDE;
        float* Out = (mat == 0) ? g_A : (mat == 1) ? g_Bm : g_H;
        u32 wb0 = s2u(&Wh[(wn * 16 + l8) * XW_STRIDE + lb * 4]);
        u32 wb1 = s2u(&Wh[(wn * 16 + 8 + l8) * XW_STRIDE + lb * 4]);

        float c[2][2][4];
#pragma unroll
        for (int mt = 0; mt < 2; mt++)
#pragma unroll
            for (int nt = 0; nt < 2; nt++)
#pragma unroll
                for (int q = 0; q < 4; q++) c[mt][nt][q] = 0.f;

#pragma unroll
        for (int ck = 0; ck < 16; ck++) {
            u32 koff = ck * 8 * 4;
            u32 a[2][4], bfr[2][2];
            ldsm4(a[0][0], a[0][1], a[0][2], a[0][3], xb0 + koff);
            ldsm4(a[1][0], a[1][1], a[1][2], a[1][3], xb1 + koff);
            ldsm2(bfr[0][0], bfr[0][1], wb0 + koff);
            ldsm2(bfr[1][0], bfr[1][1], wb1 + koff);
#pragma unroll
            for (int mt = 0; mt < 2; mt++)
#pragma unroll
                for (int nt = 0; nt < 2; nt++)
                    mma_f16(c[mt][nt], a[mt], bfr[nt]);
        }

#pragma unroll
        for (int mt = 0; mt < 2; mt++) {
            int row = m0 + wm * 32 + mt * 16 + lg;
#pragma unroll
            for (int nt = 0; nt < 2; nt++) {
                int col = n0 + wn * 16 + nt * 8 + 2 * lk;
                *(float2*)(Out + row * Dx + col)       = make_float2(c[mt][nt][0], c[mt][nt][1]);
                *(float2*)(Out + (row + 8) * Dx + col) = make_float2(c[mt][nt][2], c[mt][nt][3]);
            }
        }
    }
}

// ---------------------------------------------------------------------------
// Kernel 2: edge scores + mask + softmax -> g_W, tail casts folded in. (R8)
// ---------------------------------------------------------------------------
__global__ __launch_bounds__(256) void edge_kernel(
    const int* __restrict__ dep,
    const float* __restrict__ w2,
    const int* __restrict__ wl,
    float* __restrict__ dst)   // out + BLD, or nullptr
{
    int b  = blockIdx.y;
    int i0 = blockIdx.x * 8;

    __shared__ __align__(16) float Ash2[8][520];
    __shared__ __align__(16) float w2d[512];
    __shared__ __align__(16) float Bt[2][16][258];
    __shared__ float redmx[2][8], redsum[2][8];

    int tid = threadIdx.x;

#pragma unroll
    for (int p = 0; p < 2; p++) {
        int e = tid * 4 + p * 1024;
        int il = e >> 8, cc = e & 255;
        float4 v = *(const float4*)(g_A + (b * Lx + i0 + il) * Dx + cc);
        *(u64*)&Ash2[il][2 * cc]     = pack2(v.x, v.x);
        *(u64*)&Ash2[il][2 * cc + 2] = pack2(v.y, v.y);
        *(u64*)&Ash2[il][2 * cc + 4] = pack2(v.z, v.z);
        *(u64*)&Ash2[il][2 * cc + 6] = pack2(v.w, v.w);
    }
    {
        float v = w2[tid];
        *(u64*)&w2d[2 * tid] = pack2(v, v);
    }
    if (dst && blockIdx.x == 0 && blockIdx.y == 0 && tid < Bx)
        dst[tid] = (float)wl[tid];
    float* depout = dst ? dst + Bx : nullptr;

    const float* Bbase = g_Bm + b * Lx * Dx;

    float4 pf[4];
#pragma unroll
    for (int p = 0; p < 4; p++) {
        int e = tid * 4 + p * 1024;
        int j = e >> 4, cl = e & 15;
        pf[p] = *(const float4*)(Bbase + j * Dx + cl);
    }
#pragma unroll
    for (int p = 0; p < 4; p++) {
        int e = tid * 4 + p * 1024;
        int j = e >> 4, cl = e & 15;
        Bt[0][cl + 0][j] = pf[p].x; Bt[0][cl + 1][j] = pf[p].y;
        Bt[0][cl + 2][j] = pf[p].z; Bt[0][cl + 3][j] = pf[p].w;
    }
    __syncthreads();

    int w  = tid >> 5;
    int jl = tid & 31;
    int jh = w >> 2;
    int wr = w & 3;
    int r0 = wr * 2, r1 = r0 + 1;
    int jbase = jh * 128;

    u64 acc0[2] = {0, 0}, acc1[2] = {0, 0};

#pragma unroll 1
    for (int ch = 0; ch < 16; ch++) {
        int buf = ch & 1;
        if (ch < 15) {
            int c0 = (ch + 1) * 16;
#pragma unroll
            for (int p = 0; p < 4; p++) {
                int e = tid * 4 + p * 1024;
                int j = e >> 4, cl = e & 15;
                pf[p] = *(const float4*)(Bbase + j * Dx + c0 + cl);
            }
        }
#pragma unroll
        for (int c2 = 0; c2 < 8; c2++) {
            int cbase = ch * 16 + c2 * 2;
            ulonglong2 A0 = *(const ulonglong2*)&Ash2[r0][cbase * 2];
            ulonglong2 A1 = *(const ulonglong2*)&Ash2[r1][cbase * 2];
            ulonglong2 UU = *(const ulonglong2*)&w2d[cbase * 2];
#pragma unroll
            for (int cc = 0; cc < 2; cc++) {
                u64 a0 = cc ? A0.y : A0.x;
                u64 a1 = cc ? A1.y : A1.x;
                u64 up = cc ? UU.y : UU.x;
                int cl = c2 * 2 + cc;
#pragma unroll
                for (int gp = 0; gp < 2; gp++) {
                    u64 bt = *(const u64*)&Bt[buf][cl][jbase + gp * 64 + jl * 2];
                    acc0[gp] = ffma2(fmax2z(fadd2(a0, bt)), up, acc0[gp]);
                    acc1[gp] = ffma2(fmax2z(fadd2(a1, bt)), up, acc1[gp]);
                }
            }
        }
        if (ch < 15) {
            int nb = buf ^ 1;
#pragma unroll
            for (int p = 0; p < 4; p++) {
                int e = tid * 4 + p * 1024;
                int j = e >> 4, cl = e & 15;
                Bt[nb][cl + 0][j] = pf[p].x; Bt[nb][cl + 1][j] = pf[p].y;
                Bt[nb][cl + 2][j] = pf[p].z; Bt[nb][cl + 3][j] = pf[p].w;
            }
            __syncthreads();
        }
    }

    int gi0 = b * Lx + i0 + r0;
    int gi1 = b * Lx + i0 + r1;
    float T0[4], T1[4];
    int   mk0[4], mk1[4];
    float mx0 = -1e30f, mx1 = -1e30f;
#pragma unroll
    for (int gp = 0; gp < 2; gp++) {
        int j0 = jbase + gp * 64 + jl * 2;
        int2 m0v = *(const int2*)(dep + gi0 * Lx + j0);
        int2 m1v = *(const int2*)(dep + gi1 * Lx + j0);
        float lo, hi;
        unpack2(acc0[gp], lo, hi);
        mk0[2*gp]   = (m0v.x > 0);
        mk0[2*gp+1] = (m0v.y > 0);
        T0[2*gp]    = mk0[2*gp]   ? lo : -100.0f;
        T0[2*gp+1]  = mk0[2*gp+1] ? hi : -100.0f;
        unpack2(acc1[gp], lo, hi);
        mk1[2*gp]   = (m1v.x > 0);
        mk1[2*gp+1] = (m1v.y > 0);
        T1[2*gp]    = mk1[2*gp]   ? lo : -100.0f;
        T1[2*gp+1]  = mk1[2*gp+1] ? hi : -100.0f;
        mx0 = fmaxf(mx0, fmaxf(T0[2*gp], T0[2*gp+1]));
        mx1 = fmaxf(mx1, fmaxf(T1[2*gp], T1[2*gp+1]));
        if (depout) {
            *(float2*)(depout + gi0 * Lx + j0) = make_float2((float)m0v.x, (float)m0v.y);
            *(float2*)(depout + gi1 * Lx + j0) = make_float2((float)m1v.x, (float)m1v.y);
        }
    }
#pragma unroll
    for (int off = 16; off > 0; off >>= 1) {
        mx0 = fmaxf(mx0, __shfl_xor_sync(0xffffffffu, mx0, off));
        mx1 = fmaxf(mx1, __shfl_xor_sync(0xffffffffu, mx1, off));
    }
    if (jl == 0) { redmx[jh][r0] = mx0; redmx[jh][r1] = mx1; }
    __syncthreads();
    float gmx0 = fmaxf(redmx[0][r0], redmx[1][r0]);
    float gmx1 = fmaxf(redmx[0][r1], redmx[1][r1]);

    float E0[4], E1[4], sum0 = 0.f, sum1 = 0.f;
#pragma unroll
    for (int g = 0; g < 4; g++) {
        E0[g] = expf(T0[g] - gmx0); sum0 += E0[g];
        E1[g] = expf(T1[g] - gmx1); sum1 += E1[g];
    }
#pragma unroll
    for (int off = 16; off > 0; off >>= 1) {
        sum0 += __shfl_xor_sync(0xffffffffu, sum0, off);
        sum1 += __shfl_xor_sync(0xffffffffu, sum1, off);
    }
    if (jl == 0) { redsum[jh][r0] = sum0; redsum[jh][r1] = sum1; }
    __syncthreads();
    float inv0 = 1.0f / (redsum[0][r0] + redsum[1][r0]);
    float inv1 = 1.0f / (redsum[0][r1] + redsum[1][r1]);

#pragma unroll
    for (int gp = 0; gp < 2; gp++) {
        int j0 = jbase + gp * 64 + jl * 2;
        float2 o0, o1;
        o0.x = mk0[2*gp]   ? E0[2*gp]   * inv0 : 0.f;
        o0.y = mk0[2*gp+1] ? E0[2*gp+1] * inv0 : 0.f;
        o1.x = mk1[2*gp]   ? E1[2*gp]   * inv1 : 0.f;
        o1.y = mk1[2*gp+1] ? E1[2*gp+1] * inv1 : 0.f;
        *(float2*)(g_W + gi0 * Lx + j0) = o0;
        *(float2*)(g_W + gi1 * Lx + j0) = o1;
    }
}

// ---------------------------------------------------------------------------
// Kernel 3: agg via fp16 HMMA + ldmatrix (A-side). out = relu(Q + w@H). (R15)
// Block 64i x 64c, 256 thr = 8 warps (2m32 x 4n16), warp tile 32x16.
// Wt [i][kp] stride 132 (LDSM.x4 A-side); Hs [kp][c] stride 72 (plain LDS).
// grid (4,4,8) = 128 blocks.
// ---------------------------------------------------------------------------
#define AGG_SMEM ((64 * XW_STRIDE + 128 * 72) * 4)

__global__ __launch_bounds__(256) void agg_kernel(
    const float* __restrict__ Q,
    float* __restrict__ out)
{
    extern __shared__ u32 sm[];
    u32* Wt = sm;                       // [i][kp], stride 132
    u32* Hs = sm + 64 * XW_STRIDE;      // [kp][c], stride 72

    int b  = blockIdx.z;
    int i0 = blockIdx.x * 64;
    int c0 = blockIdx.y * 64;

    int tid = threadIdx.x;
    int wid = tid >> 5, lane = tid & 31;
    int wm = wid & 1;
    int wn = wid >> 1;
    int lg = lane >> 2, lk = lane & 3;

    // ---- stage all W (64 rows x 256 j), coalesced
#pragma unroll
    for (int p = 0; p < 16; p++) {
        int idx = p * 256 + tid;
        int row = idx >> 6, c4 = idx & 63;
        float4 v = *(const float4*)(g_W + (b * Lx + i0 + row) * Lx + c4 * 4);
        *(u64*)&Wt[row * XW_STRIDE + c4 * 2] = packh4(v);
    }
    // ---- stage all H (256 j x 64 c)
#pragma unroll
    for (int p = 0; p < 16; p++) {
        int idx = p * 256 + tid;
        int kp = idx >> 5, c2 = (idx & 31) * 2;
        const float* Hg = g_H + (b * Lx + 2 * kp) * Dx + c0 + c2;
        float2 h0 = *(const float2*)Hg;
        float2 h1 = *(const float2*)(Hg + Dx);
        Hs[kp * 72 + c2]     = h2u(h0.x, h1.x);
        Hs[kp * 72 + c2 + 1] = h2u(h0.y, h1.y);
    }
    __syncthreads();

    int lm = lane & 15, lh = lane >> 4;
    u32 wb0 = s2u(&Wt[(wm * 32 + lm) * XW_STRIDE + lh * 4]);
    u32 wb1 = s2u(&Wt[(wm * 32 + 16 + lm) * XW_STRIDE + lh * 4]);

    float c[2][2][4];
#pragma unroll
    for (int mt = 0; mt < 2; mt++)
#pragma unroll
        for (int nt = 0; nt < 2; nt++)
#pragma unroll
            for (int q = 0; q < 4; q++) c[mt][nt][q] = 0.f;

#pragma unroll
    for (int ck = 0; ck < 16; ck++) {
        int kc = ck * 8;
        u32 koff = (u32)kc * 4;
        u32 a[2][4], bfr[2][2];
        ldsm4(a[0][0], a[0][1], a[0][2], a[0][3], wb0 + koff);
        ldsm4(a[1][0], a[1][1], a[1][2], a[1][3], wb1 + koff);
#pragma unroll
        for (int nt = 0; nt < 2; nt++) {
            int cb = wn * 16 + nt * 8;
            bfr[nt][0] = Hs[(kc + lk) * 72 + cb + lg];
            bfr[nt][1] = Hs[(kc + lk + 4) * 72 + cb + lg];
        }
#pragma unroll
        for (int mt = 0; mt < 2; mt++)
#pragma unroll
            for (int nt = 0; nt < 2; nt++)
                mma_f16(c[mt][nt], a[mt], bfr[nt]);
    }

#pragma unroll
    for (int mt = 0; mt < 2; mt++) {
        int row = i0 + wm * 32 + mt * 16 + lg;
#pragma unroll
        for (int nt = 0; nt < 2; nt++) {
            int col = c0 + wn * 16 + nt * 8 + 2 * lk;
            long base0 = (long)(b * Lx + row) * Dx + col;
            long base1 = (long)(b * Lx + row + 8) * Dx + col;
            float2 q0 = *(const float2*)(Q + base0);
            float2 q1 = *(const float2*)(Q + base1);
            *(float2*)(out + base0) = make_float2(fmaxf(q0.x + c[mt][nt][0], 0.f),
                                                  fmaxf(q0.y + c[mt][nt][1], 0.f));
            *(float2*)(out + base1) = make_float2(fmaxf(q1.x + c[mt][nt][2], 0.f),
                                                  fmaxf(q1.y + c[mt][nt][3], 0.f));
        }
    }
}

// ---------------------------------------------------------------------------
extern "C" void kernel_launch(void* const* d_in, const int* in_sizes, int n_in,
                              void* d_out, int out_size)
{
    const float* Q   = (const float*)d_in[0];
    const int*   wl  = (const int*)d_in[1];
    const int*   dep = (const int*)d_in[2];
    const float* Wa  = (const float*)d_in[3];
    const float* Wb  = (const float*)d_in[4];
    const float* w2  = (const float*)d_in[5];
    const float* Wd  = (const float*)d_in[6];
    float* out = (float*)d_out;

    float* dst = (out_size >= BLD + Bx + BLL) ? out + BLD : nullptr;

    static bool attr_set = false;
    if (!attr_set) {
        cudaFuncSetAttribute(proj_kernel, cudaFuncAttributeMaxDynamicSharedMemorySize, PROJ_SMEM);
        cudaFuncSetAttribute(agg_kernel,  cudaFuncAttributeMaxDynamicSharedMemorySize, AGG_SMEM);
        attr_set = true;
    }

    // all 3 projections fused per CTA (128 CTAs, 1 wave)
    proj_kernel<<<dim3(32, 4), 256, PROJ_SMEM>>>(Q, Wa, Wb, Wd);
    // edge scores + softmax -> g_W (+ tail casts) (256 blocks)
    edge_kernel<<<dim3(32, Bx), 256>>>(dep, w2, wl, dst);
    // aggregation via fp16 HMMA + ldmatrix A-side + fused residual relu
    agg_kernel<<<dim3(4, 4, Bx), 256, AGG_SMEM>>>(Q, out);
}

// round 17
// speedup vs baseline: 1.1525x; 1.1453x over previous
#include <cuda_runtime.h>
#include <cuda_fp16.h>

// Problem constants
#define Bx 8
#define Lx 256
#define Dx 256
#define BLD (Bx*Lx*Dx)   // 524288
#define BLL (Bx*Lx*Lx)   // 524288

typedef unsigned int u32;
typedef unsigned long long u64;

// Scratch (device globals — no allocation allowed)
__device__ float g_A[BLD], g_Bm[BLD], g_H[BLD];
__device__ float g_W[BLL];

// ---- fp16 m16n8k16 mma (fp32 accum) ---------------------------------------
__device__ __forceinline__ void mma_f16(float c[4], const u32 a[4], const u32 b[2]) {
    asm volatile(
        "mma.sync.aligned.m16n8k16.row.col.f32.f16.f16.f32 "
        "{%0,%1,%2,%3},{%4,%5,%6,%7},{%8,%9},{%0,%1,%2,%3};"
        : "+f"(c[0]), "+f"(c[1]), "+f"(c[2]), "+f"(c[3])
        : "r"(a[0]), "r"(a[1]), "r"(a[2]), "r"(a[3]), "r"(b[0]), "r"(b[1]));
}
__device__ __forceinline__ u32 h2u(float x, float y) {
    __half2 h = __floats2half2_rn(x, y);
    return *reinterpret_cast<u32*>(&h);
}
__device__ __forceinline__ u64 packh4(float4 v) {
    return ((u64)h2u(v.z, v.w) << 32) | (u64)h2u(v.x, v.y);
}

// ---- packed f32x2 helpers (edge kernel) ------------------------------------
__device__ __forceinline__ u64 pack2(float lo, float hi) {
    u64 r; asm("mov.b64 %0,{%1,%2};" : "=l"(r) : "f"(lo), "f"(hi)); return r;
}
__device__ __forceinline__ void unpack2(u64 v, float& lo, float& hi) {
    asm("mov.b64 {%0,%1},%2;" : "=f"(lo), "=f"(hi) : "l"(v));
}
__device__ __forceinline__ u64 ffma2(u64 a, u64 b, u64 c) {
    u64 d; asm("fma.rn.f32x2 %0,%1,%2,%3;" : "=l"(d) : "l"(a), "l"(b), "l"(c)); return d;
}
__device__ __forceinline__ u64 fadd2(u64 a, u64 b) {
    u64 d; asm("add.rn.f32x2 %0,%1,%2;" : "=l"(d) : "l"(a), "l"(b)); return d;
}
__device__ __forceinline__ u64 fmax2z(u64 a) {
    float lo, hi; unpack2(a, lo, hi);
    return pack2(fmaxf(lo, 0.f), fmaxf(hi, 0.f));
}

// ---------------------------------------------------------------------------
// Kernel 1: projections via fp16 HMMA, full-K coalesced staging. (R13 exact)
// Block 64m x 64n, 256 thr = 8 warps (2m32 x 4n16), warp tile 32x16.
// ---------------------------------------------------------------------------
#define XW_STRIDE 132
#define PROJ_SMEM (2 * 64 * XW_STRIDE * 4)

__global__ __launch_bounds__(256) void proj_kernel(
    const float* __restrict__ Q,
    const float* __restrict__ Wa,
    const float* __restrict__ Wb,
    const float* __restrict__ Wd)
{
    extern __shared__ u32 sm[];
    u32* Xh = sm;                        // [row][kp], stride 132
    u32* Wh = sm + 64 * XW_STRIDE;

    int mat = blockIdx.z;
    const float* W = (mat == 0) ? Wa : (mat == 1) ? Wb : Wd;
    float* Out     = (mat == 0) ? g_A : (mat == 1) ? g_Bm : g_H;

    int tid  = threadIdx.x;
    int m0 = blockIdx.x * 64, n0 = blockIdx.y * 64;
    int wid = tid >> 5, lane = tid & 31;
    int wm = wid & 1;
    int wn = wid >> 1;
    int lg = lane >> 2, lk = lane & 3;

#pragma unroll
    for (int p = 0; p < 16; p++) {
        int idx = p * 256 + tid;
        int row = idx >> 6, c4 = idx & 63;
        float4 xv = *(const float4*)(Q + (m0 + row) * Dx + c4 * 4);
        float4 wv = *(const float4*)(W + (n0 + row) * Dx + c4 * 4);
        *(u64*)&Xh[row * XW_STRIDE + c4 * 2] = packh4(xv);
        *(u64*)&Wh[row * XW_STRIDE + c4 * 2] = packh4(wv);
    }
    __syncthreads();

    float c[2][2][4];
#pragma unroll
    for (int mt = 0; mt < 2; mt++)
#pragma unroll
        for (int nt = 0; nt < 2; nt++)
#pragma unroll
            for (int q = 0; q < 4; q++) c[mt][nt][q] = 0.f;

#pragma unroll
    for (int ck = 0; ck < 16; ck++) {
        int kc = ck * 8;
        u32 a[2][4], bfr[2][2];
#pragma unroll
        for (int mt = 0; mt < 2; mt++) {
            int mb = wm * 32 + mt * 16;
            a[mt][0] = Xh[(mb + lg) * XW_STRIDE + kc + lk];
            a[mt][1] = Xh[(mb + lg + 8) * XW_STRIDE + kc + lk];
            a[mt][2] = Xh[(mb + lg) * XW_STRIDE + kc + lk + 4];
            a[mt][3] = Xh[(mb + lg + 8) * XW_STRIDE + kc + lk + 4];
        }
#pragma unroll
        for (int nt = 0; nt < 2; nt++) {
            int nb = wn * 16 + nt * 8;
            bfr[nt][0] = Wh[(nb + lg) * XW_STRIDE + kc + lk];
            bfr[nt][1] = Wh[(nb + lg) * XW_STRIDE + kc + lk + 4];
        }
#pragma unroll
        for (int mt = 0; mt < 2; mt++)
#pragma unroll
            for (int nt = 0; nt < 2; nt++)
                mma_f16(c[mt][nt], a[mt], bfr[nt]);
    }

#pragma unroll
    for (int mt = 0; mt < 2; mt++) {
        int row = m0 + wm * 32 + mt * 16 + lg;
#pragma unroll
        for (int nt = 0; nt < 2; nt++) {
            int col = n0 + wn * 16 + nt * 8 + 2 * lk;
            *(float2*)(Out + row * Dx + col)       = make_float2(c[mt][nt][0], c[mt][nt][1]);
            *(float2*)(Out + (row + 8) * Dx + col) = make_float2(c[mt][nt][2], c[mt][nt][3]);
        }
    }
}

// ---------------------------------------------------------------------------
// Kernel 2: edge scores + mask + softmax -> g_W. 16 ROWS PER BLOCK.
// Block = (b, 16 rows), 256 thr = 8 warps; warp = (j-half jh, row-quad wr).
// Each warp owns 4 rows: bt loaded once serves 4 rows (Bt LDS/row halved,
// Bm restaging halved). Dynamic smem (68.6 KB). grid (16, Bx) = 128 blocks.
// ---------------------------------------------------------------------------
#define ASH_OFF 0                    // [16][520]
#define W2D_OFF (16 * 520)           // [512]
#define BT_OFF  (W2D_OFF + 512)      // [2][16][258]
#define RMX_OFF (BT_OFF + 2 * 16 * 258)  // [2][16]
#define RSM_OFF (RMX_OFF + 32)           // [2][16]
#define EDGE_SMEM ((RSM_OFF + 32) * 4)

__global__ __launch_bounds__(256) void edge_kernel(
    const int* __restrict__ dep,
    const float* __restrict__ w2,
    const int* __restrict__ wl,
    float* __restrict__ dst)   // out + BLD, or nullptr
{
    extern __shared__ float smf[];
    float* Ash2 = smf + ASH_OFF;     // [row][520] dup pairs
    float* w2d  = smf + W2D_OFF;
    float* Bt   = smf + BT_OFF;      // [buf][cl][258]
    float* rmx  = smf + RMX_OFF;     // [jh][16]
    float* rsm  = smf + RSM_OFF;

    int b  = blockIdx.y;
    int i0 = blockIdx.x * 16;
    int tid = threadIdx.x;

    // stage 16 A rows, duplicated pairs
#pragma unroll
    for (int p = 0; p < 4; p++) {
        int e = tid * 4 + p * 1024;
        int il = e >> 8, cc = e & 255;
        float4 v = *(const float4*)(g_A + (b * Lx + i0 + il) * Dx + cc);
        float* row = Ash2 + il * 520;
        *(u64*)&row[2 * cc]     = pack2(v.x, v.x);
        *(u64*)&row[2 * cc + 2] = pack2(v.y, v.y);
        *(u64*)&row[2 * cc + 4] = pack2(v.z, v.z);
        *(u64*)&row[2 * cc + 6] = pack2(v.w, v.w);
    }
    {
        float v = w2[tid];
        *(u64*)&w2d[2 * tid] = pack2(v, v);
    }
    if (dst && blockIdx.x == 0 && blockIdx.y == 0 && tid < Bx)
        dst[tid] = (float)wl[tid];
    float* depout = dst ? dst + Bx : nullptr;

    const float* Bbase = g_Bm + b * Lx * Dx;

    float4 pf[4];
#pragma unroll
    for (int p = 0; p < 4; p++) {
        int e = tid * 4 + p * 1024;
        int j = e >> 4, cl = e & 15;
        pf[p] = *(const float4*)(Bbase + j * Dx + cl);
    }
#pragma unroll
    for (int p = 0; p < 4; p++) {
        int e = tid * 4 + p * 1024;
        int j = e >> 4, cl = e & 15;
        Bt[(cl + 0) * 258 + j] = pf[p].x; Bt[(cl + 1) * 258 + j] = pf[p].y;
        Bt[(cl + 2) * 258 + j] = pf[p].z; Bt[(cl + 3) * 258 + j] = pf[p].w;
    }
    __syncthreads();

    int w  = tid >> 5;
    int jl = tid & 31;
    int jh = w >> 2;         // j-half 0/1
    int wr = w & 3;          // row quad
    int rb = wr * 4;         // local row base (4 rows per warp)
    int jbase = jh * 128;

    u64 acc[4][2];
#pragma unroll
    for (int r = 0; r < 4; r++) { acc[r][0] = 0ull; acc[r][1] = 0ull; }

#pragma unroll 1
    for (int ch = 0; ch < 16; ch++) {
        int buf = ch & 1;
        float* Btb = Bt + buf * 16 * 258;
        if (ch < 15) {
            int c0 = (ch + 1) * 16;
#pragma unroll
            for (int p = 0; p < 4; p++) {
                int e = tid * 4 + p * 1024;
                int j = e >> 4, cl = e & 15;
                pf[p] = *(const float4*)(Bbase + j * Dx + c0 + cl);
            }
        }
#pragma unroll
        for (int c2 = 0; c2 < 8; c2++) {
            int cbase = ch * 16 + c2 * 2;
            ulonglong2 A0 = *(const ulonglong2*)&Ash2[(rb + 0) * 520 + cbase * 2];
            ulonglong2 A1 = *(const ulonglong2*)&Ash2[(rb + 1) * 520 + cbase * 2];
            ulonglong2 A2 = *(const ulonglong2*)&Ash2[(rb + 2) * 520 + cbase * 2];
            ulonglong2 A3 = *(const ulonglong2*)&Ash2[(rb + 3) * 520 + cbase * 2];
            ulonglong2 UU = *(const ulonglong2*)&w2d[cbase * 2];
#pragma unroll
            for (int cc = 0; cc < 2; cc++) {
                u64 a0 = cc ? A0.y : A0.x;
                u64 a1 = cc ? A1.y : A1.x;
                u64 a2 = cc ? A2.y : A2.x;
                u64 a3 = cc ? A3.y : A3.x;
                u64 up = cc ? UU.y : UU.x;
                int cl = c2 * 2 + cc;
#pragma unroll
                for (int gp = 0; gp < 2; gp++) {
                    u64 bt = *(const u64*)&Btb[cl * 258 + jbase + gp * 64 + jl * 2];
                    acc[0][gp] = ffma2(fmax2z(fadd2(a0, bt)), up, acc[0][gp]);
                    acc[1][gp] = ffma2(fmax2z(fadd2(a1, bt)), up, acc[1][gp]);
                    acc[2][gp] = ffma2(fmax2z(fadd2(a2, bt)), up, acc[2][gp]);
                    acc[3][gp] = ffma2(fmax2z(fadd2(a3, bt)), up, acc[3][gp]);
                }
            }
        }
        if (ch < 15) {
            float* Btn = Bt + (buf ^ 1) * 16 * 258;
#pragma unroll
            for (int p = 0; p < 4; p++) {
                int e = tid * 4 + p * 1024;
                int j = e >> 4, cl = e & 15;
                Btn[(cl + 0) * 258 + j] = pf[p].x; Btn[(cl + 1) * 258 + j] = pf[p].y;
                Btn[(cl + 2) * 258 + j] = pf[p].z; Btn[(cl + 3) * 258 + j] = pf[p].w;
            }
            __syncthreads();
        }
    }

    // ---- masked softmax for 4 rows, merged across the two j-half warps ----
    float T[4][4];
    int   mkb[4];
    float mx[4];
#pragma unroll
    for (int r = 0; r < 4; r++) {
        int gi = b * Lx + i0 + rb + r;
        mkb[r] = 0;
        mx[r] = -1e30f;
#pragma unroll
        for (int gp = 0; gp < 2; gp++) {
            int j0 = jbase + gp * 64 + jl * 2;
            int2 mv = *(const int2*)(dep + gi * Lx + j0);
            float lo, hi; unpack2(acc[r][gp], lo, hi);
            int g0 = 2 * gp, g1 = 2 * gp + 1;
            if (mv.x > 0) mkb[r] |= 1 << g0;
            if (mv.y > 0) mkb[r] |= 1 << g1;
            T[r][g0] = (mv.x > 0) ? lo : -100.0f;
            T[r][g1] = (mv.y > 0) ? hi : -100.0f;
            mx[r] = fmaxf(mx[r], fmaxf(T[r][g0], T[r][g1]));
            if (depout)
                *(float2*)(depout + gi * Lx + j0) =
                    make_float2((float)mv.x, (float)mv.y);
        }
#pragma unroll
        for (int off = 16; off > 0; off >>= 1)
            mx[r] = fmaxf(mx[r], __shfl_xor_sync(0xffffffffu, mx[r], off));
    }
    if (jl == 0) {
#pragma unroll
        for (int r = 0; r < 4; r++) rmx[jh * 16 + rb + r] = mx[r];
    }
    __syncthreads();

    float sum[4];
#pragma unroll
    for (int r = 0; r < 4; r++) {
        float gmx = fmaxf(rmx[rb + r], rmx[16 + rb + r]);
        sum[r] = 0.f;
#pragma unroll
        for (int g = 0; g < 4; g++) {
            T[r][g] = expf(T[r][g] - gmx);
            sum[r] += T[r][g];
        }
#pragma unroll
        for (int off = 16; off > 0; off >>= 1)
            sum[r] += __shfl_xor_sync(0xffffffffu, sum[r], off);
    }
    if (jl == 0) {
#pragma unroll
        for (int r = 0; r < 4; r++) rsm[jh * 16 + rb + r] = sum[r];
    }
    __syncthreads();

#pragma unroll
    for (int r = 0; r < 4; r++) {
        float inv = 1.0f / (rsm[rb + r] + rsm[16 + rb + r]);
        int gi = b * Lx + i0 + rb + r;
#pragma unroll
        for (int gp = 0; gp < 2; gp++) {
            int j0 = jbase + gp * 64 + jl * 2;
            float2 o;
            o.x = (mkb[r] >> (2 * gp)     & 1) ? T[r][2 * gp]     * inv : 0.f;
            o.y = (mkb[r] >> (2 * gp + 1) & 1) ? T[r][2 * gp + 1] * inv : 0.f;
            *(float2*)(g_W + gi * Lx + j0) = o;
        }
    }
}

// ---------------------------------------------------------------------------
// Kernel 3: agg via fp16 HMMA, full-K staging, coalesced. (R13 exact)
// Block 32i x 64c, 256 thr = 8 warps (2m16 x 4n16), warp tile 16x16.
// ---------------------------------------------------------------------------
#define AGG_SMEM ((32 * XW_STRIDE + 128 * 72) * 4)

__global__ __launch_bounds__(256) void agg_kernel(
    const float* __restrict__ Q,
    float* __restrict__ out)
{
    extern __shared__ u32 sm[];
    u32* Wt = sm;                       // [i][kp], stride 132
    u32* Hs = sm + 32 * XW_STRIDE;      // [kp][c], stride 72

    int b  = blockIdx.z;
    int i0 = blockIdx.x * 32;
    int c0 = blockIdx.y * 64;

    int tid = threadIdx.x;
    int wid = tid >> 5, lane = tid & 31;
    int wm = wid & 1;
    int wn = wid >> 1;
    int lg = lane >> 2, lk = lane & 3;

#pragma unroll
    for (int p = 0; p < 8; p++) {
        int idx = p * 256 + tid;
        int row = idx >> 6, c4 = idx & 63;
        float4 v = *(const float4*)(g_W + (b * Lx + i0 + row) * Lx + c4 * 4);
        *(u64*)&Wt[row * XW_STRIDE + c4 * 2] = packh4(v);
    }
#pragma unroll
    for (int p = 0; p < 16; p++) {
        int idx = p * 256 + tid;
        int kp = idx >> 5, c2 = (idx & 31) * 2;
        const float* Hg = g_H + (b * Lx + 2 * kp) * Dx + c0 + c2;
        float2 h0 = *(const float2*)Hg;
        float2 h1 = *(const float2*)(Hg + Dx);
        Hs[kp * 72 + c2]     = h2u(h0.x, h1.x);
        Hs[kp * 72 + c2 + 1] = h2u(h0.y, h1.y);
    }
    __syncthreads();

    float c[2][4];
#pragma unroll
    for (int nt = 0; nt < 2; nt++)
#pragma unroll
        for (int q = 0; q < 4; q++) c[nt][q] = 0.f;

#pragma unroll
    for (int ck = 0; ck < 16; ck++) {
        int kc = ck * 8;
        u32 a[4], bfr[2][2];
        int mb = wm * 16;
        a[0] = Wt[(mb + lg) * XW_STRIDE + kc + lk];
        a[1] = Wt[(mb + lg + 8) * XW_STRIDE + kc + lk];
        a[2] = Wt[(mb + lg) * XW_STRIDE + kc + lk + 4];
        a[3] = Wt[(mb + lg + 8) * XW_STRIDE + kc + lk + 4];
#pragma unroll
        for (int nt = 0; nt < 2; nt++) {
            int cb = wn * 16 + nt * 8;
            bfr[nt][0] = Hs[(kc + lk) * 72 + cb + lg];
            bfr[nt][1] = Hs[(kc + lk + 4) * 72 + cb + lg];
        }
#pragma unroll
        for (int nt = 0; nt < 2; nt++)
            mma_f16(c[nt], a, bfr[nt]);
    }

#pragma unroll
    for (int nt = 0; nt < 2; nt++) {
        int col  = c0 + wn * 16 + nt * 8 + 2 * lk;
        int row0 = i0 + wm * 16 + lg;
        long base0 = (long)(b * Lx + row0) * Dx + col;
        long base1 = (long)(b * Lx + row0 + 8) * Dx + col;
        float2 q0 = *(const float2*)(Q + base0);
        float2 q1 = *(const float2*)(Q + base1);
        *(float2*)(out + base0) = make_float2(fmaxf(q0.x + c[nt][0], 0.f),
                                              fmaxf(q0.y + c[nt][1], 0.f));
        *(float2*)(out + base1) = make_float2(fmaxf(q1.x + c[nt][2], 0.f),
                                              fmaxf(q1.y + c[nt][3], 0.f));
    }
}

// ---------------------------------------------------------------------------
extern "C" void kernel_launch(void* const* d_in, const int* in_sizes, int n_in,
                              void* d_out, int out_size)
{
    const float* Q   = (const float*)d_in[0];
    const int*   wl  = (const int*)d_in[1];
    const int*   dep = (const int*)d_in[2];
    const float* Wa  = (const float*)d_in[3];
    const float* Wb  = (const float*)d_in[4];
    const float* w2  = (const float*)d_in[5];
    const float* Wd  = (const float*)d_in[6];
    float* out = (float*)d_out;

    float* dst = (out_size >= BLD + Bx + BLL) ? out + BLD : nullptr;

    static bool attr_set = false;
    if (!attr_set) {
        cudaFuncSetAttribute(proj_kernel, cudaFuncAttributeMaxDynamicSharedMemorySize, PROJ_SMEM);
        cudaFuncSetAttribute(edge_kernel, cudaFuncAttributeMaxDynamicSharedMemorySize, EDGE_SMEM);
        cudaFuncSetAttribute(agg_kernel,  cudaFuncAttributeMaxDynamicSharedMemorySize, AGG_SMEM);
        attr_set = true;
    }

    // projections via fp16 HMMA, coalesced full-K staging (384 blocks)
    proj_kernel<<<dim3(32, 4, 3), 256, PROJ_SMEM>>>(Q, Wa, Wb, Wd);
    // edge scores + softmax -> g_W (+ tail casts), 16 rows/block (128 blocks)
    edge_kernel<<<dim3(16, Bx), 256, EDGE_SMEM>>>(dep, w2, wl, dst);
    // aggregation via fp16 HMMA + fused residual relu (256 blocks)
    agg_kernel<<<dim3(8, 4, Bx), 256, AGG_SMEM>>>(Q, out);
}